// round 12
// baseline (speedup 1.0000x reference)
#include <cuda_runtime.h>
#include <cuda_fp16.h>

#define NN 100000
#define EE 1600000
#define DD 64
#define GR 128
#define SCAN_B 1024
#define NB ((NN + SCAN_B - 1) / SCAN_B)   // 98
#define NBLK 592                           // 4 blocks/SM x 148 SMs, all co-resident
#define NWARP (NBLK * 8)

// ---------------- scratch (static __device__, zero-initialized) -------------
__device__ int    g_deg_out[NN];
__device__ int    g_deg_in[NN];
__device__ float  g_norm_src[NN];
__device__ float  g_norm_dst[NN];
__device__ int    g_row_ptr[NN + 1];   // block-local exclusive; add g_bsum[i>>10]
__device__ int    g_fill[NN];
__device__ int    g_col[EE];
__device__ int    g_bsum[NB];
__device__ __half g_h[NN * DD];
__device__ float  g_bufA[NN * DD];
__device__ float  g_bufB[NN * DD];

// ---------------- software grid barrier (sense-reversing, monotonic gen) ----
__device__ unsigned           g_bcount = 0;
__device__ volatile unsigned  g_bgen   = 0;

__device__ __forceinline__ void gbar() {
    __syncthreads();
    if (threadIdx.x == 0) {
        unsigned gen = g_bgen;
        __threadfence();
        if (atomicAdd(&g_bcount, 1u) == NBLK - 1u) {
            g_bcount = 0u;
            __threadfence();
            g_bgen = gen + 1u;
        } else {
            while (g_bgen == gen) { __nanosleep(32); }
            __threadfence();
        }
    }
    __syncthreads();
}

// ---------------- degree histogram (deg/fill zero on entry: static zero-init
// on first run, re-zeroed inside k_scan1 on every run) -----------------------
__global__ void k_hist(const int* __restrict__ src, const int* __restrict__ dst) {
    int e = (blockIdx.x * blockDim.x + threadIdx.x) * 2;
    if (e + 1 < EE) {
        int s0 = src[e], s1 = src[e + 1];
        int d0 = dst[e], d1 = dst[e + 1];
        atomicAdd(&g_deg_out[s0], 1);
        atomicAdd(&g_deg_out[s1], 1);
        atomicAdd(&g_deg_in[d0], 1);
        atomicAdd(&g_deg_in[d1], 1);
    } else if (e < EE) {
        atomicAdd(&g_deg_out[src[e]], 1);
        atomicAdd(&g_deg_in[dst[e]], 1);
    }
}

// ---------------- scan1: block-local exclusive scan of deg_in + norms -------
// also read-then-clear deg arrays and zero g_fill for this call's fill phase.
__global__ void k_scan1() {
    __shared__ int sh[SCAN_B];
    int tid = threadIdx.x;
    int i   = blockIdx.x * SCAN_B + tid;
    int v   = 0;
    if (i < NN) {
        int din  = g_deg_in[i];
        int dout = g_deg_out[i];
        v = din;
        g_deg_in[i]  = 0;          // consumed; zero for next call's k_hist
        g_deg_out[i] = 0;
        g_fill[i]    = 0;          // zero before this call's fill phase
        if (din  < 1) din  = 1;
        if (dout < 1) dout = 1;
        g_norm_src[i] = rsqrtf((float)dout);
        g_norm_dst[i] = rsqrtf((float)din);
    }
    sh[tid] = v;
    __syncthreads();
    for (int off = 1; off < SCAN_B; off <<= 1) {
        int t = (tid >= off) ? sh[tid - off] : 0;
        __syncthreads();
        sh[tid] += t;
        __syncthreads();
    }
    int incl = sh[tid];
    if (i < NN) g_row_ptr[i] = incl - v;        // exclusive within block
    if (tid == SCAN_B - 1) g_bsum[blockIdx.x] = incl;   // block total
}

// ---------------- fused-kernel phase bodies ----------------

// CSR fill, all blocks, 4-edge ILP (compensates reduced 592-block concurrency)
__device__ __forceinline__ void fill_dev(const int* __restrict__ src,
                                         const int* __restrict__ dst) {
    const int STR = NBLK * 256;
    int e = blockIdx.x * 256 + threadIdx.x;
    for (; e + 3 * STR < EE; e += 4 * STR) {
        int d0 = __ldg(&dst[e]);
        int d1 = __ldg(&dst[e + STR]);
        int d2 = __ldg(&dst[e + 2 * STR]);
        int d3 = __ldg(&dst[e + 3 * STR]);
        int s0 = __ldg(&src[e]);
        int s1 = __ldg(&src[e + STR]);
        int s2 = __ldg(&src[e + 2 * STR]);
        int s3 = __ldg(&src[e + 3 * STR]);
        int r0 = g_row_ptr[d0] + g_bsum[d0 >> 10];
        int r1 = g_row_ptr[d1] + g_bsum[d1 >> 10];
        int r2 = g_row_ptr[d2] + g_bsum[d2 >> 10];
        int r3 = g_row_ptr[d3] + g_bsum[d3 >> 10];
        int p0 = r0 + atomicAdd(&g_fill[d0], 1);
        int p1 = r1 + atomicAdd(&g_fill[d1], 1);
        int p2 = r2 + atomicAdd(&g_fill[d2], 1);
        int p3 = r3 + atomicAdd(&g_fill[d3], 1);
        g_col[p0] = s0;
        g_col[p1] = s1;
        g_col[p2] = s2;
        g_col[p3] = s3;
    }
    for (; e < EE; e += STR) {
        int d = __ldg(&dst[e]);
        int pos = g_row_ptr[d] + g_bsum[d >> 10] + atomicAdd(&g_fill[d], 1);
        g_col[pos] = __ldg(&src[e]);
    }
}

// GEMM phase: h = fp16((x * norm_src) @ W). R9/R11's proven 256-thread shape:
// thread (rc=tid>>4, g=tid&15) does 8 rows x 4 cols; all smem reads float4.
__device__ __forceinline__ void gemm_dev(const float* __restrict__ x,
                                         const float* __restrict__ W,
                                         float4* Ws4, float4* xs4) {
    int tid = threadIdx.x;
    {
        const float4* Wsrc = (const float4*)W;
        #pragma unroll
        for (int i = tid; i < DD * 16; i += 256) Ws4[i] = Wsrc[i];
    }

    int rc = tid >> 4;
    int g  = tid & 15;

    const int n_tiles = (NN + GR - 1) / GR;
    for (int t = blockIdx.x; t < n_tiles; t += NBLK) {
        int base = t * GR;

        __syncthreads();   // prev tile's xs readers done (covers W on iter 0)
        #pragma unroll
        for (int i = 0; i < 8; i++) {
            int idx = tid + i * 256;
            int row = idx >> 4;
            int kq  = idx & 15;
            int n   = base + row;
            float4 v = make_float4(0.f, 0.f, 0.f, 0.f);
            float ns = 0.f;
            if (n < NN) {
                v  = ((const float4*)x)[n * 16 + kq];
                ns = g_norm_src[n];
            }
            v.x *= ns; v.y *= ns; v.z *= ns; v.w *= ns;
            xs4[row * 16 + kq] = v;
        }
        __syncthreads();

        float4 acc[8];
        #pragma unroll
        for (int j = 0; j < 8; j++) acc[j] = make_float4(0.f, 0.f, 0.f, 0.f);

        #pragma unroll
        for (int kq = 0; kq < 16; kq++) {
            float4 w0 = Ws4[(4 * kq + 0) * 16 + g];
            float4 w1 = Ws4[(4 * kq + 1) * 16 + g];
            float4 w2 = Ws4[(4 * kq + 2) * 16 + g];
            float4 w3 = Ws4[(4 * kq + 3) * 16 + g];
            #pragma unroll
            for (int j = 0; j < 8; j++) {
                float4 xv = xs4[(rc * 8 + j) * 16 + kq];
                acc[j].x += xv.x * w0.x; acc[j].y += xv.x * w0.y;
                acc[j].z += xv.x * w0.z; acc[j].w += xv.x * w0.w;
                acc[j].x += xv.y * w1.x; acc[j].y += xv.y * w1.y;
                acc[j].z += xv.y * w1.z; acc[j].w += xv.y * w1.w;
                acc[j].x += xv.z * w2.x; acc[j].y += xv.z * w2.y;
                acc[j].z += xv.z * w2.z; acc[j].w += xv.z * w2.w;
                acc[j].x += xv.w * w3.x; acc[j].y += xv.w * w3.y;
                acc[j].z += xv.w * w3.z; acc[j].w += xv.w * w3.w;
            }
        }

        #pragma unroll
        for (int j = 0; j < 8; j++) {
            int n = base + rc * 8 + j;
            if (n < NN) {
                __half2 lo = __floats2half2_rn(acc[j].x, acc[j].y);
                __half2 hi = __floats2half2_rn(acc[j].z, acc[j].w);
                uint2 pk;
                pk.x = *(unsigned int*)&lo;
                pk.y = *(unsigned int*)&hi;
                ((uint2*)g_h)[n * 16 + g] = pk;
            }
        }
    }
}

// aggregation + epilogue phase: warp per node, grid-stride, 8 edges in flight.
// out[n] = relu(segsum(h[src]) * norm_dst[n] + b) + resid[n]
__device__ __forceinline__ void agg_dev(const float* __restrict__ resid,
                                        const float* __restrict__ b,
                                        float* __restrict__ out) {
    int gwid = (blockIdx.x * 256 + threadIdx.x) >> 5;
    int lane = threadIdx.x & 31;
    const __half2* h2 = (const __half2*)g_h;
    float2 bb = ((const float2*)b)[lane];

    for (int n = gwid; n < NN; n += NWARP) {
        int beg = g_row_ptr[n] + g_bsum[n >> 10];
        int end = g_row_ptr[n + 1] + g_bsum[(n + 1) >> 10];

        float2 a0 = make_float2(0.f, 0.f);
        float2 a1 = make_float2(0.f, 0.f);
        float2 a2 = make_float2(0.f, 0.f);
        float2 a3 = make_float2(0.f, 0.f);
        int i = beg;
        for (; i + 7 < end; i += 8) {
            int s0 = __ldg(&g_col[i]);
            int s1 = __ldg(&g_col[i + 1]);
            int s2 = __ldg(&g_col[i + 2]);
            int s3 = __ldg(&g_col[i + 3]);
            int s4 = __ldg(&g_col[i + 4]);
            int s5 = __ldg(&g_col[i + 5]);
            int s6 = __ldg(&g_col[i + 6]);
            int s7 = __ldg(&g_col[i + 7]);
            float2 v0 = __half22float2(h2[s0 * 32 + lane]);
            float2 v1 = __half22float2(h2[s1 * 32 + lane]);
            float2 v2 = __half22float2(h2[s2 * 32 + lane]);
            float2 v3 = __half22float2(h2[s3 * 32 + lane]);
            float2 v4 = __half22float2(h2[s4 * 32 + lane]);
            float2 v5 = __half22float2(h2[s5 * 32 + lane]);
            float2 v6 = __half22float2(h2[s6 * 32 + lane]);
            float2 v7 = __half22float2(h2[s7 * 32 + lane]);
            a0.x += v0.x; a0.y += v0.y;
            a1.x += v1.x; a1.y += v1.y;
            a2.x += v2.x; a2.y += v2.y;
            a3.x += v3.x; a3.y += v3.y;
            a0.x += v4.x; a0.y += v4.y;
            a1.x += v5.x; a1.y += v5.y;
            a2.x += v6.x; a2.y += v6.y;
            a3.x += v7.x; a3.y += v7.y;
        }
        if (i + 3 < end) {
            int s0 = __ldg(&g_col[i]);
            int s1 = __ldg(&g_col[i + 1]);
            int s2 = __ldg(&g_col[i + 2]);
            int s3 = __ldg(&g_col[i + 3]);
            float2 v0 = __half22float2(h2[s0 * 32 + lane]);
            float2 v1 = __half22float2(h2[s1 * 32 + lane]);
            float2 v2 = __half22float2(h2[s2 * 32 + lane]);
            float2 v3 = __half22float2(h2[s3 * 32 + lane]);
            a0.x += v0.x; a0.y += v0.y;
            a1.x += v1.x; a1.y += v1.y;
            a2.x += v2.x; a2.y += v2.y;
            a3.x += v3.x; a3.y += v3.y;
            i += 4;
        }
        for (; i < end; i++) {
            int s0 = __ldg(&g_col[i]);
            float2 v0 = __half22float2(h2[s0 * 32 + lane]);
            a0.x += v0.x; a0.y += v0.y;
        }
        float sx = (a0.x + a1.x) + (a2.x + a3.x);
        float sy = (a0.y + a1.y) + (a2.y + a3.y);

        float nd = g_norm_dst[n];
        float2 rr = ((const float2*)resid)[n * 32 + lane];
        float2 o;
        o.x = fmaxf(sx * nd + bb.x, 0.f) + rr.x;
        o.y = fmaxf(sy * nd + bb.y, 0.f) + rr.y;
        ((float2*)out)[n * 32 + lane] = o;
    }
}

// ---------------- the persistent fused kernel ----------------
// phases: scan2(block0) | fill | gemm1 | agg1 | gemm2 | agg2 | gemm3 | agg3
// separated by software grid barriers. All NBLK blocks co-resident
// (launch_bounds(256,4) caps regs; 48KB static smem <= 57KB/block at 4/SM).
__global__ void __launch_bounds__(256, 4) k_fused(
    const float* __restrict__ feat,
    const int* __restrict__ src, const int* __restrict__ dst,
    const float* __restrict__ w1, const float* __restrict__ b1,
    const float* __restrict__ w2, const float* __restrict__ b2,
    const float* __restrict__ w3, const float* __restrict__ b3,
    float* __restrict__ bufA, float* __restrict__ bufB,
    float* __restrict__ out)
{
    __shared__ float4 sW[DD * 16];   // 16 KB
    __shared__ float4 sX[GR * 16];   // 32 KB

    // phase 0: scan2 (block 0 only; 98 block sums, 256-thread scan in sX)
    if (blockIdx.x == 0) {
        int* sh = (int*)sX;
        int tid = threadIdx.x;
        int v = (tid < NB) ? g_bsum[tid] : 0;
        sh[tid] = v;
        __syncthreads();
        for (int off = 1; off < 256; off <<= 1) {
            int t = (tid >= off) ? sh[tid - off] : 0;
            __syncthreads();
            sh[tid] += t;
            __syncthreads();
        }
        if (tid < NB) g_bsum[tid] = sh[tid] - v;     // exclusive
        if (tid == NB - 1) g_row_ptr[NN] = v;        // last block's own total
    }
    gbar();

    fill_dev(src, dst);
    gbar();

    gemm_dev(feat, w1, sW, sX);
    gbar();
    agg_dev(feat, b1, bufA);
    gbar();

    gemm_dev(bufA, w2, sW, sX);
    gbar();
    agg_dev(bufA, b2, bufB);
    gbar();

    gemm_dev(bufB, w3, sW, sX);
    gbar();
    agg_dev(bufB, b3, out);
}

// ---------------- launch ----------------
extern "C" void kernel_launch(void* const* d_in, const int* in_sizes, int n_in,
                              void* d_out, int out_size) {
    const float* feat = (const float*)d_in[0];
    const int*   src  = (const int*)d_in[1];
    const int*   dst  = (const int*)d_in[2];
    // d_in[3] = etype (unused)
    const float* w1 = (const float*)d_in[4];
    const float* b1 = (const float*)d_in[5];
    const float* w2 = (const float*)d_in[6];
    const float* b2 = (const float*)d_in[7];
    const float* w3 = (const float*)d_in[8];
    const float* b3 = (const float*)d_in[9];
    float* out = (float*)d_out;

    void *pa = nullptr, *pb = nullptr;
    cudaGetSymbolAddress(&pa, g_bufA);
    cudaGetSymbolAddress(&pb, g_bufB);
    float* bufA = (float*)pa;
    float* bufB = (float*)pb;

    const int gE2 = (EE / 2 + 255) / 256;

    k_hist<<<gE2, 256>>>(src, dst);
    k_scan1<<<NB, SCAN_B>>>();
    k_fused<<<NBLK, 256>>>(feat, src, dst, w1, b1, w2, b2, w3, b3,
                           bufA, bufB, out);
}

// round 14
// speedup vs baseline: 1.1393x; 1.1393x over previous
#include <cuda_runtime.h>
#include <cuda_fp16.h>

#define NN 100000
#define EE 1600000
#define DD 64
#define GR 128
#define SCAN_B 1024
#define NB ((NN + SCAN_B - 1) / SCAN_B)   // 98

// ---------------- scratch (static __device__, zero-initialized) -------------
__device__ int    g_deg_out[NN];
__device__ int    g_deg_in[NN];
__device__ float  g_norm_src[NN];
__device__ float  g_norm_dst[NN];
__device__ int    g_row_ptr[NN + 1];   // block-local exclusive; add g_bsum[i>>10]
__device__ int    g_fill[NN];
__device__ int    g_col[EE];
__device__ int    g_bsum[NB];
__device__ __half g_h[NN * DD];
__device__ float  g_bufA[NN * DD];
__device__ float  g_bufB[NN * DD];

// ---------------- split histograms (deg arrays zero on entry: static
// zero-init first run; re-zeroed by their consumers every run) ---------------
__global__ void k_hist_in(const int* __restrict__ dst) {
    int e = (blockIdx.x * blockDim.x + threadIdx.x) * 2;
    if (e + 1 < EE) {
        int d0 = dst[e], d1 = dst[e + 1];
        atomicAdd(&g_deg_in[d0], 1);
        atomicAdd(&g_deg_in[d1], 1);
    } else if (e < EE) {
        atomicAdd(&g_deg_in[dst[e]], 1);
    }
}

__global__ void k_hist_out(const int* __restrict__ src) {
    int e = (blockIdx.x * blockDim.x + threadIdx.x) * 2;
    if (e + 1 < EE) {
        int s0 = src[e], s1 = src[e + 1];
        atomicAdd(&g_deg_out[s0], 1);
        atomicAdd(&g_deg_out[s1], 1);
    } else if (e < EE) {
        atomicAdd(&g_deg_out[src[e]], 1);
    }
}

// norm_src = rsqrt(max(deg_out,1)) — elementwise, no scan. Clears deg_out.
__global__ void k_norm_src() {
    int i = blockIdx.x * blockDim.x + threadIdx.x;
    if (i < NN) {
        int d = g_deg_out[i];
        g_deg_out[i] = 0;
        if (d < 1) d = 1;
        g_norm_src[i] = rsqrtf((float)d);
    }
}

// ---------------- scan1 (R11-proven body, deg_in side only) ----------------
// block-local exclusive scan of deg_in; computes norm_dst; clears deg_in/fill.
__global__ void k_scan1() {
    __shared__ int sh[SCAN_B];
    int tid = threadIdx.x;
    int i   = blockIdx.x * SCAN_B + tid;
    int v   = 0;
    if (i < NN) {
        int din = g_deg_in[i];
        v = din;
        g_deg_in[i] = 0;           // consumed; zero for next call's hist
        g_fill[i]   = 0;           // zero before this call's k_fill
        if (din < 1) din = 1;
        g_norm_dst[i] = rsqrtf((float)din);
    }
    sh[tid] = v;
    __syncthreads();
    for (int off = 1; off < SCAN_B; off <<= 1) {
        int t = (tid >= off) ? sh[tid - off] : 0;
        __syncthreads();
        sh[tid] += t;
        __syncthreads();
    }
    int incl = sh[tid];
    if (i < NN) g_row_ptr[i] = incl - v;        // exclusive within block
    if (tid == SCAN_B - 1) g_bsum[blockIdx.x] = incl;   // block total
}

// scan2 (R11-proven): exclusive-scan the 98 block totals in place.
// row_ptr[NN] gets the LAST BLOCK's own total so that
// row_ptr[NN] + g_bsum[NN>>10] == EE  (NN>>10 == NB-1 == 97).
__global__ void k_scan2() {
    __shared__ int sh[128];
    int tid = threadIdx.x;
    int v = (tid < NB) ? g_bsum[tid] : 0;
    sh[tid] = v;
    __syncthreads();
    for (int off = 1; off < 128; off <<= 1) {
        int t = (tid >= off) ? sh[tid - off] : 0;
        __syncthreads();
        sh[tid] += t;
        __syncthreads();
    }
    if (tid < NB) g_bsum[tid] = sh[tid] - v;    // exclusive
    if (tid == NB - 1) g_row_ptr[NN] = v;       // last block's own total
}

// ---------------- CSR fill (grouped by dst); bsum offset applied inline ------
__global__ void k_fill(const int* __restrict__ src, const int* __restrict__ dst) {
    int e = blockIdx.x * blockDim.x + threadIdx.x;
    if (e < EE) {
        int d   = dst[e];
        int pos = g_row_ptr[d] + g_bsum[d >> 10] + atomicAdd(&g_fill[d], 1);
        g_col[pos] = src[e];
    }
}

// ---------------- GEMM: h[n] = fp16( (x[n] * norm_src[n]) @ W ) --------------
// (proven R9/R11 shape) 128-row tiles, 256 threads, thread (rc,g) does
// 8 rows x 4 cols; all smem reads float4. smem = 48KB exact.
__global__ void k_gemm(const float* __restrict__ x, const float* __restrict__ W,
                       __half* __restrict__ h) {
    __shared__ float4 Ws4[DD * 16];
    __shared__ float4 xs4[GR * 16];
    int tid = threadIdx.x;

    {
        const float4* Wsrc = (const float4*)W;
        #pragma unroll
        for (int i = tid; i < DD * 16; i += 256) Ws4[i] = Wsrc[i];
    }

    int rc = tid >> 4;
    int g  = tid & 15;

    const int n_tiles = (NN + GR - 1) / GR;
    for (int t = blockIdx.x; t < n_tiles; t += gridDim.x) {
        int base = t * GR;

        __syncthreads();
        #pragma unroll
        for (int i = 0; i < 8; i++) {
            int idx = tid + i * 256;
            int row = idx >> 4;
            int kq  = idx & 15;
            int n   = base + row;
            float4 v = make_float4(0.f, 0.f, 0.f, 0.f);
            float ns = 0.f;
            if (n < NN) {
                v  = ((const float4*)x)[n * 16 + kq];
                ns = g_norm_src[n];
            }
            v.x *= ns; v.y *= ns; v.z *= ns; v.w *= ns;
            xs4[row * 16 + kq] = v;
        }
        __syncthreads();

        float4 acc[8];
        #pragma unroll
        for (int j = 0; j < 8; j++) acc[j] = make_float4(0.f, 0.f, 0.f, 0.f);

        #pragma unroll
        for (int kq = 0; kq < 16; kq++) {
            float4 w0 = Ws4[(4 * kq + 0) * 16 + g];
            float4 w1 = Ws4[(4 * kq + 1) * 16 + g];
            float4 w2 = Ws4[(4 * kq + 2) * 16 + g];
            float4 w3 = Ws4[(4 * kq + 3) * 16 + g];
            #pragma unroll
            for (int j = 0; j < 8; j++) {
                float4 xv = xs4[(rc * 8 + j) * 16 + kq];
                acc[j].x += xv.x * w0.x; acc[j].y += xv.x * w0.y;
                acc[j].z += xv.x * w0.z; acc[j].w += xv.x * w0.w;
                acc[j].x += xv.y * w1.x; acc[j].y += xv.y * w1.y;
                acc[j].z += xv.y * w1.z; acc[j].w += xv.y * w1.w;
                acc[j].x += xv.z * w2.x; acc[j].y += xv.z * w2.y;
                acc[j].z += xv.z * w2.z; acc[j].w += xv.z * w2.w;
                acc[j].x += xv.w * w3.x; acc[j].y += xv.w * w3.y;
                acc[j].z += xv.w * w3.z; acc[j].w += xv.w * w3.w;
            }
        }

        #pragma unroll
        for (int j = 0; j < 8; j++) {
            int n = base + rc * 8 + j;
            if (n < NN) {
                __half2 lo = __floats2half2_rn(acc[j].x, acc[j].y);
                __half2 hi = __floats2half2_rn(acc[j].z, acc[j].w);
                uint2 pk;
                pk.x = *(unsigned int*)&lo;
                pk.y = *(unsigned int*)&hi;
                ((uint2*)h)[n * 16 + g] = pk;
            }
        }
    }
}

// ---------------- aggregation + epilogue (proven R11 shape) ----------------
__global__ void k_agg(const float* __restrict__ resid, const float* __restrict__ b,
                      float* __restrict__ out) {
    int warp = (blockIdx.x * blockDim.x + threadIdx.x) >> 5;
    int lane = threadIdx.x & 31;
    if (warp >= NN) return;

    int beg = g_row_ptr[warp] + g_bsum[warp >> 10];
    int end = g_row_ptr[warp + 1] + g_bsum[(warp + 1) >> 10];
    const __half2* h2 = (const __half2*)g_h;

    float2 a0 = make_float2(0.f, 0.f);
    float2 a1 = make_float2(0.f, 0.f);
    float2 a2 = make_float2(0.f, 0.f);
    float2 a3 = make_float2(0.f, 0.f);
    int i = beg;
    for (; i + 7 < end; i += 8) {
        int s0 = __ldg(&g_col[i]);
        int s1 = __ldg(&g_col[i + 1]);
        int s2 = __ldg(&g_col[i + 2]);
        int s3 = __ldg(&g_col[i + 3]);
        int s4 = __ldg(&g_col[i + 4]);
        int s5 = __ldg(&g_col[i + 5]);
        int s6 = __ldg(&g_col[i + 6]);
        int s7 = __ldg(&g_col[i + 7]);
        float2 v0 = __half22float2(h2[s0 * 32 + lane]);
        float2 v1 = __half22float2(h2[s1 * 32 + lane]);
        float2 v2 = __half22float2(h2[s2 * 32 + lane]);
        float2 v3 = __half22float2(h2[s3 * 32 + lane]);
        float2 v4 = __half22float2(h2[s4 * 32 + lane]);
        float2 v5 = __half22float2(h2[s5 * 32 + lane]);
        float2 v6 = __half22float2(h2[s6 * 32 + lane]);
        float2 v7 = __half22float2(h2[s7 * 32 + lane]);
        a0.x += v0.x; a0.y += v0.y;
        a1.x += v1.x; a1.y += v1.y;
        a2.x += v2.x; a2.y += v2.y;
        a3.x += v3.x; a3.y += v3.y;
        a0.x += v4.x; a0.y += v4.y;
        a1.x += v5.x; a1.y += v5.y;
        a2.x += v6.x; a2.y += v6.y;
        a3.x += v7.x; a3.y += v7.y;
    }
    if (i + 3 < end) {
        int s0 = __ldg(&g_col[i]);
        int s1 = __ldg(&g_col[i + 1]);
        int s2 = __ldg(&g_col[i + 2]);
        int s3 = __ldg(&g_col[i + 3]);
        float2 v0 = __half22float2(h2[s0 * 32 + lane]);
        float2 v1 = __half22float2(h2[s1 * 32 + lane]);
        float2 v2 = __half22float2(h2[s2 * 32 + lane]);
        float2 v3 = __half22float2(h2[s3 * 32 + lane]);
        a0.x += v0.x; a0.y += v0.y;
        a1.x += v1.x; a1.y += v1.y;
        a2.x += v2.x; a2.y += v2.y;
        a3.x += v3.x; a3.y += v3.y;
        i += 4;
    }
    for (; i < end; i++) {
        int s0 = __ldg(&g_col[i]);
        float2 v0 = __half22float2(h2[s0 * 32 + lane]);
        a0.x += v0.x; a0.y += v0.y;
    }
    float sx = (a0.x + a1.x) + (a2.x + a3.x);
    float sy = (a0.y + a1.y) + (a2.y + a3.y);

    float nd = g_norm_dst[warp];
    float2 bb = ((const float2*)b)[lane];
    float2 rr = ((const float2*)resid)[warp * 32 + lane];
    float2 o;
    o.x = fmaxf(sx * nd + bb.x, 0.f) + rr.x;
    o.y = fmaxf(sy * nd + bb.y, 0.f) + rr.y;
    ((float2*)out)[warp * 32 + lane] = o;
}

// ---------------- launch ----------------
extern "C" void kernel_launch(void* const* d_in, const int* in_sizes, int n_in,
                              void* d_out, int out_size) {
    const float* feat = (const float*)d_in[0];
    const int*   src  = (const int*)d_in[1];
    const int*   dst  = (const int*)d_in[2];
    // d_in[3] = etype (unused)
    const float* w1 = (const float*)d_in[4];
    const float* b1 = (const float*)d_in[5];
    const float* w2 = (const float*)d_in[6];
    const float* b2 = (const float*)d_in[7];
    const float* w3 = (const float*)d_in[8];
    const float* b3 = (const float*)d_in[9];
    float* out = (float*)d_out;

    void *ph = nullptr, *pa = nullptr, *pb = nullptr;
    cudaGetSymbolAddress(&ph, g_h);
    cudaGetSymbolAddress(&pa, g_bufA);
    cudaGetSymbolAddress(&pb, g_bufB);
    __half* h   = (__half*)ph;
    float* bufA = (float*)pa;
    float* bufB = (float*)pb;

    // lazily-created side stream + events: first call (the uncaptured
    // correctness run) creates them; every call issues IDENTICAL work.
    static cudaStream_t s_side = nullptr;
    static cudaEvent_t  ev_fork = nullptr, ev_join = nullptr;
    if (s_side == nullptr) {
        cudaStreamCreateWithFlags(&s_side, cudaStreamNonBlocking);
        cudaEventCreateWithFlags(&ev_fork, cudaEventDisableTiming);
        cudaEventCreateWithFlags(&ev_join, cudaEventDisableTiming);
    }

    const int gN    = (NN + 255) / 256;
    const int gE    = (EE + 255) / 256;
    const int gE2   = (EE / 2 + 255) / 256;
    const int gAgg  = (NN * 32 + 255) / 256;
    const int gGemm = (NN + GR - 1) / GR;

    // ---- fork immediately: side = hist_out -> norm_src -> gemm1 ----
    cudaEventRecord(ev_fork, 0);
    cudaStreamWaitEvent(s_side, ev_fork, 0);
    k_hist_out<<<gE2, 256, 0, s_side>>>(src);
    k_norm_src<<<gN, 256, 0, s_side>>>();
    k_gemm<<<gGemm, 256, 0, s_side>>>(feat, w1, h);
    cudaEventRecord(ev_join, s_side);

    // ---- main: hist_in -> scan1 -> scan2 -> fill ----
    k_hist_in<<<gE2, 256>>>(dst);
    k_scan1<<<NB, SCAN_B>>>();
    k_scan2<<<1, 128>>>();
    k_fill<<<gE, 256>>>(src, dst);

    // ---- join, then the serial layer chain ----
    cudaStreamWaitEvent(0, ev_join, 0);
    k_agg<<<gAgg, 256>>>(feat, b1, bufA);

    k_gemm<<<gGemm, 256>>>(bufA, w2, h);
    k_agg<<<gAgg, 256>>>(bufA, b2, bufB);

    k_gemm<<<gGemm, 256>>>(bufB, w3, h);
    k_agg<<<gAgg, 256>>>(bufB, b3, out);
}

// round 16
// speedup vs baseline: 1.4146x; 1.2416x over previous
#include <cuda_runtime.h>
#include <cuda_fp16.h>

#define NN 100000
#define EE 1600000
#define DD 64
#define GR 128
#define SCAN_B 1024
#define NB ((NN + SCAN_B - 1) / SCAN_B)   // 98

// ---------------- scratch (static __device__, zero-initialized) -------------
__device__ int    g_deg_out[NN];
__device__ int    g_deg_in[NN];
__device__ float  g_norm_src[NN];
__device__ float  g_norm_dst[NN];
__device__ int    g_row_ptr[NN + 1];   // block-local exclusive; add g_bsum[i>>10]
__device__ int    g_fill[NN];
__device__ int    g_col[EE];
__device__ int    g_bsum[NB];
__device__ __half g_h[NN * DD];
__device__ float  g_bufA[NN * DD];
__device__ float  g_bufB[NN * DD];

// ---------------- fused degree histogram (deg/fill zero on entry: static
// zero-init first run, re-zeroed inside k_scan1 on every run) ----------------
__global__ void k_hist(const int* __restrict__ src, const int* __restrict__ dst) {
    int e = (blockIdx.x * blockDim.x + threadIdx.x) * 2;
    if (e + 1 < EE) {
        int s0 = src[e], s1 = src[e + 1];
        int d0 = dst[e], d1 = dst[e + 1];
        atomicAdd(&g_deg_out[s0], 1);
        atomicAdd(&g_deg_out[s1], 1);
        atomicAdd(&g_deg_in[d0], 1);
        atomicAdd(&g_deg_in[d1], 1);
    } else if (e < EE) {
        atomicAdd(&g_deg_out[src[e]], 1);
        atomicAdd(&g_deg_in[dst[e]], 1);
    }
}

// ---------------- scan1 (R11-proven): block-local scan of deg_in + norms,
// read-then-clear deg arrays, zero g_fill ------------------------------------
__global__ void k_scan1() {
    __shared__ int sh[SCAN_B];
    int tid = threadIdx.x;
    int i   = blockIdx.x * SCAN_B + tid;
    int v   = 0;
    if (i < NN) {
        int din  = g_deg_in[i];
        int dout = g_deg_out[i];
        v = din;
        g_deg_in[i]  = 0;
        g_deg_out[i] = 0;
        g_fill[i]    = 0;
        if (din  < 1) din  = 1;
        if (dout < 1) dout = 1;
        g_norm_src[i] = rsqrtf((float)dout);
        g_norm_dst[i] = rsqrtf((float)din);
    }
    sh[tid] = v;
    __syncthreads();
    for (int off = 1; off < SCAN_B; off <<= 1) {
        int t = (tid >= off) ? sh[tid - off] : 0;
        __syncthreads();
        sh[tid] += t;
        __syncthreads();
    }
    int incl = sh[tid];
    if (i < NN) g_row_ptr[i] = incl - v;
    if (tid == SCAN_B - 1) g_bsum[blockIdx.x] = incl;
}

// scan2 (R11-proven): exclusive-scan the 98 block totals in place.
// row_ptr[NN] + g_bsum[97] == EE.
__global__ void k_scan2() {
    __shared__ int sh[128];
    int tid = threadIdx.x;
    int v = (tid < NB) ? g_bsum[tid] : 0;
    sh[tid] = v;
    __syncthreads();
    for (int off = 1; off < 128; off <<= 1) {
        int t = (tid >= off) ? sh[tid - off] : 0;
        __syncthreads();
        sh[tid] += t;
        __syncthreads();
    }
    if (tid < NB) g_bsum[tid] = sh[tid] - v;
    if (tid == NB - 1) g_row_ptr[NN] = v;
}

// ---------------- CSR fill (grouped by dst); bsum offset applied inline ------
__global__ void k_fill(const int* __restrict__ src, const int* __restrict__ dst) {
    int e = blockIdx.x * blockDim.x + threadIdx.x;
    if (e < EE) {
        int d   = dst[e];
        int pos = g_row_ptr[d] + g_bsum[d >> 10] + atomicAdd(&g_fill[d], 1);
        g_col[pos] = src[e];
    }
}

// ---------------- GEMM (R11-proven): h[n] = fp16((x[n]*norm_src[n]) @ W) -----
__global__ void k_gemm(const float* __restrict__ x, const float* __restrict__ W,
                       __half* __restrict__ h) {
    __shared__ float4 Ws4[DD * 16];
    __shared__ float4 xs4[GR * 16];
    int tid = threadIdx.x;

    {
        const float4* Wsrc = (const float4*)W;
        #pragma unroll
        for (int i = tid; i < DD * 16; i += 256) Ws4[i] = Wsrc[i];
    }

    int rc = tid >> 4;
    int g  = tid & 15;

    const int n_tiles = (NN + GR - 1) / GR;
    for (int t = blockIdx.x; t < n_tiles; t += gridDim.x) {
        int base = t * GR;

        __syncthreads();
        #pragma unroll
        for (int i = 0; i < 8; i++) {
            int idx = tid + i * 256;
            int row = idx >> 4;
            int kq  = idx & 15;
            int n   = base + row;
            float4 v = make_float4(0.f, 0.f, 0.f, 0.f);
            float ns = 0.f;
            if (n < NN) {
                v  = ((const float4*)x)[n * 16 + kq];
                ns = g_norm_src[n];
            }
            v.x *= ns; v.y *= ns; v.z *= ns; v.w *= ns;
            xs4[row * 16 + kq] = v;
        }
        __syncthreads();

        float4 acc[8];
        #pragma unroll
        for (int j = 0; j < 8; j++) acc[j] = make_float4(0.f, 0.f, 0.f, 0.f);

        #pragma unroll
        for (int kq = 0; kq < 16; kq++) {
            float4 w0 = Ws4[(4 * kq + 0) * 16 + g];
            float4 w1 = Ws4[(4 * kq + 1) * 16 + g];
            float4 w2 = Ws4[(4 * kq + 2) * 16 + g];
            float4 w3 = Ws4[(4 * kq + 3) * 16 + g];
            #pragma unroll
            for (int j = 0; j < 8; j++) {
                float4 xv = xs4[(rc * 8 + j) * 16 + kq];
                acc[j].x += xv.x * w0.x; acc[j].y += xv.x * w0.y;
                acc[j].z += xv.x * w0.z; acc[j].w += xv.x * w0.w;
                acc[j].x += xv.y * w1.x; acc[j].y += xv.y * w1.y;
                acc[j].z += xv.y * w1.z; acc[j].w += xv.y * w1.w;
                acc[j].x += xv.z * w2.x; acc[j].y += xv.z * w2.y;
                acc[j].z += xv.z * w2.z; acc[j].w += xv.z * w2.w;
                acc[j].x += xv.w * w3.x; acc[j].y += xv.w * w3.y;
                acc[j].z += xv.w * w3.z; acc[j].w += xv.w * w3.w;
            }
        }

        #pragma unroll
        for (int j = 0; j < 8; j++) {
            int n = base + rc * 8 + j;
            if (n < NN) {
                __half2 lo = __floats2half2_rn(acc[j].x, acc[j].y);
                __half2 hi = __floats2half2_rn(acc[j].z, acc[j].w);
                uint2 pk;
                pk.x = *(unsigned int*)&lo;
                pk.y = *(unsigned int*)&hi;
                ((uint2*)h)[n * 16 + g] = pk;
            }
        }
    }
}

// ---------------- aggregation + epilogue: HALF-WARP per node ----------------
// 16-lane group per node; lane owns 4 cols (uint2 = 8B of fp16) so one
// warp-level gather instruction moves TWO nodes' rows. Grid covers NN exactly.
// out[n] = relu(segsum(h[src]) * norm_dst[n] + b) + resid[n]
__global__ void k_agg(const float* __restrict__ resid, const float* __restrict__ b,
                      float* __restrict__ out) {
    int node = (blockIdx.x * blockDim.x + threadIdx.x) >> 4;   // exact cover
    int sub  = threadIdx.x & 15;

    int beg = g_row_ptr[node] + g_bsum[node >> 10];
    int end = g_row_ptr[node + 1] + g_bsum[(node + 1) >> 10];
    const uint2* hrow = (const uint2*)g_h;   // 16 uint2 per 64-col fp16 row

    float4 accA = make_float4(0.f, 0.f, 0.f, 0.f);
    float4 accB = make_float4(0.f, 0.f, 0.f, 0.f);

    for (int i = beg; i < end; i += 4) {
        uint2 v0 = make_uint2(0u, 0u);
        uint2 v1 = make_uint2(0u, 0u);
        uint2 v2 = make_uint2(0u, 0u);
        uint2 v3 = make_uint2(0u, 0u);
        {
            int s0 = __ldg(&g_col[i]);
            v0 = __ldg(&hrow[s0 * 16 + sub]);
        }
        if (i + 1 < end) {
            int s1 = __ldg(&g_col[i + 1]);
            v1 = __ldg(&hrow[s1 * 16 + sub]);
        }
        if (i + 2 < end) {
            int s2 = __ldg(&g_col[i + 2]);
            v2 = __ldg(&hrow[s2 * 16 + sub]);
        }
        if (i + 3 < end) {
            int s3 = __ldg(&g_col[i + 3]);
            v3 = __ldg(&hrow[s3 * 16 + sub]);
        }

        float2 f0a = __half22float2(*(__half2*)&v0.x);
        float2 f0b = __half22float2(*(__half2*)&v0.y);
        float2 f1a = __half22float2(*(__half2*)&v1.x);
        float2 f1b = __half22float2(*(__half2*)&v1.y);
        float2 f2a = __half22float2(*(__half2*)&v2.x);
        float2 f2b = __half22float2(*(__half2*)&v2.y);
        float2 f3a = __half22float2(*(__half2*)&v3.x);
        float2 f3b = __half22float2(*(__half2*)&v3.y);

        accA.x += f0a.x; accA.y += f0a.y; accA.z += f0b.x; accA.w += f0b.y;
        accB.x += f1a.x; accB.y += f1a.y; accB.z += f1b.x; accB.w += f1b.y;
        accA.x += f2a.x; accA.y += f2a.y; accA.z += f2b.x; accA.w += f2b.y;
        accB.x += f3a.x; accB.y += f3a.y; accB.z += f3b.x; accB.w += f3b.y;
    }

    float4 s;
    s.x = accA.x + accB.x;
    s.y = accA.y + accB.y;
    s.z = accA.z + accB.z;
    s.w = accA.w + accB.w;

    float nd = g_norm_dst[node];
    float4 bb = ((const float4*)b)[sub];
    float4 rr = ((const float4*)resid)[node * 16 + sub];
    float4 o;
    o.x = fmaxf(s.x * nd + bb.x, 0.f) + rr.x;
    o.y = fmaxf(s.y * nd + bb.y, 0.f) + rr.y;
    o.z = fmaxf(s.z * nd + bb.z, 0.f) + rr.z;
    o.w = fmaxf(s.w * nd + bb.w, 0.f) + rr.w;
    ((float4*)out)[node * 16 + sub] = o;
}

// ---------------- launch ----------------
extern "C" void kernel_launch(void* const* d_in, const int* in_sizes, int n_in,
                              void* d_out, int out_size) {
    const float* feat = (const float*)d_in[0];
    const int*   src  = (const int*)d_in[1];
    const int*   dst  = (const int*)d_in[2];
    // d_in[3] = etype (unused)
    const float* w1 = (const float*)d_in[4];
    const float* b1 = (const float*)d_in[5];
    const float* w2 = (const float*)d_in[6];
    const float* b2 = (const float*)d_in[7];
    const float* w3 = (const float*)d_in[8];
    const float* b3 = (const float*)d_in[9];
    float* out = (float*)d_out;

    void *ph = nullptr, *pa = nullptr, *pb = nullptr;
    cudaGetSymbolAddress(&ph, g_h);
    cudaGetSymbolAddress(&pa, g_bufA);
    cudaGetSymbolAddress(&pb, g_bufB);
    __half* h   = (__half*)ph;
    float* bufA = (float*)pa;
    float* bufB = (float*)pb;

    // lazily-created side stream + events: first call (the uncaptured
    // correctness run) creates them; every call issues IDENTICAL work.
    static cudaStream_t s_side = nullptr;
    static cudaEvent_t  ev_fork = nullptr, ev_join = nullptr;
    if (s_side == nullptr) {
        cudaStreamCreateWithFlags(&s_side, cudaStreamNonBlocking);
        cudaEventCreateWithFlags(&ev_fork, cudaEventDisableTiming);
        cudaEventCreateWithFlags(&ev_join, cudaEventDisableTiming);
    }

    const int gE    = (EE + 255) / 256;
    const int gE2   = (EE / 2 + 255) / 256;
    const int gAgg  = (NN * 16) / 256;      // 6250, exact cover
    const int gGemm = (NN + GR - 1) / GR;

    // ---- setup: hist -> scan1 (norms ready; deg/fill re-zeroed) ----
    k_hist<<<gE2, 256>>>(src, dst);
    k_scan1<<<NB, SCAN_B>>>();

    // ---- fork: gemm1 (needs only norm_src) overlaps scan2/fill ----
    cudaEventRecord(ev_fork, 0);
    cudaStreamWaitEvent(s_side, ev_fork, 0);
    k_gemm<<<gGemm, 256, 0, s_side>>>(feat, w1, h);
    cudaEventRecord(ev_join, s_side);

    k_scan2<<<1, 128>>>();
    k_fill<<<gE, 256>>>(src, dst);

    // ---- join, then the serial layer chain ----
    cudaStreamWaitEvent(0, ev_join, 0);
    k_agg<<<gAgg, 256>>>(feat, b1, bufA);

    k_gemm<<<gGemm, 256>>>(bufA, w2, h);
    k_agg<<<gAgg, 256>>>(bufA, b2, bufB);

    k_gemm<<<gGemm, 256>>>(bufB, w3, h);
    k_agg<<<gAgg, 256>>>(bufB, b3, out);
}